// round 1
// baseline (speedup 1.0000x reference)
#include <cuda_runtime.h>

// Problem constants
#define BB    256
#define LMAX_ 512
#define NC    300   // NCOND
#define NH    600   // NHID

// Scratch for pooled[B, NH] (no allocations allowed -> device global)
__device__ float g_pooled[BB * NH];

// ---------------- Kernel A: fused GEMM + relu + masked mean-pool ----------------
// grid = (ceil(NH/TN)=10, B), block = 128 threads
// Each block: batch b, hid-column tile [j0, j0+64). Loops over valid token
// chunks of 64, does a K-tiled (TK=20, 15 iters) register-blocked GEMM,
// relu's, and accumulates only valid rows into a per-thread pool accumulator.
constexpr int TM = 64;
constexpr int TN = 64;
constexpr int TK = 20;   // 300 = 15 * 20, no K remainder

__global__ __launch_bounds__(128, 2)
void pool_kernel(const float* __restrict__ ctx,
                 const int*   __restrict__ lengths,
                 const float* __restrict__ W1,
                 const float* __restrict__ b1)
{
    __shared__ float As[TK][TM + 1];   // [k][row], +1 pad kills write conflicts
    __shared__ float Bs[TK][TN];       // [k][col]
    __shared__ float red[16][TN];      // cross-ty reduction

    const int b   = blockIdx.y;
    const int j0  = blockIdx.x * TN;
    const int tid = threadIdx.x;
    const int tx  = tid & 7;           // col group (8)
    const int ty  = tid >> 3;          // row group (16)

    int len = lengths[b];
    if (len < 1) len = 1;

    const float* ctxb = ctx + (size_t)b * LMAX_ * NC;

    float pool[8];
#pragma unroll
    for (int c = 0; c < 8; c++) pool[c] = 0.0f;

    float bias[8];
#pragma unroll
    for (int c = 0; c < 8; c++) {
        int j = j0 + tx + 8 * c;
        bias[c] = (j < NH) ? b1[j] : 0.0f;
    }

    for (int l0 = 0; l0 < len; l0 += TM) {
        float acc[4][8];
#pragma unroll
        for (int r = 0; r < 4; r++)
#pragma unroll
            for (int c = 0; c < 8; c++) acc[r][c] = 0.0f;

        for (int k0 = 0; k0 < NC; k0 += TK) {
            // Load A tile: 64 rows x 20 k  (1280 elems, 10 per thread)
#pragma unroll
            for (int e = 0; e < 10; e++) {
                int idx = e * 128 + tid;
                int row = idx / TK;
                int kk  = idx % TK;
                int l   = l0 + row;
                As[kk][row] = (l < len) ? ctxb[(size_t)l * NC + k0 + kk] : 0.0f;
            }
            // Load B tile: 20 k x 64 cols (1280 elems, 10 per thread, coalesced over j)
#pragma unroll
            for (int e = 0; e < 10; e++) {
                int idx = e * 128 + tid;
                int kk  = idx >> 6;          // /64
                int j   = idx & 63;
                int jj  = j0 + j;
                Bs[kk][j] = (jj < NH) ? W1[(size_t)(k0 + kk) * NH + jj] : 0.0f;
            }
            __syncthreads();

#pragma unroll
            for (int k = 0; k < TK; k++) {
                float a[4], bv[8];
#pragma unroll
                for (int r = 0; r < 4; r++) a[r] = As[k][ty + 16 * r];
#pragma unroll
                for (int c = 0; c < 8; c++) bv[c] = Bs[k][tx + 8 * c];
#pragma unroll
                for (int r = 0; r < 4; r++)
#pragma unroll
                    for (int c = 0; c < 8; c++)
                        acc[r][c] = fmaf(a[r], bv[c], acc[r][c]);
            }
            __syncthreads();
        }

        // relu + accumulate only VALID rows (masking must happen pre-relu-sum
        // because relu(b1) != 0 for padded rows)
#pragma unroll
        for (int r = 0; r < 4; r++) {
            int l = l0 + ty + 16 * r;
            if (l < len) {
#pragma unroll
                for (int c = 0; c < 8; c++) {
                    float v = acc[r][c] + bias[c];
                    pool[c] += fmaxf(v, 0.0f);
                }
            }
        }
    }

    // Reduce pool across the 16 ty groups
#pragma unroll
    for (int c = 0; c < 8; c++) red[ty][tx + 8 * c] = pool[c];
    __syncthreads();

    if (tid < TN) {
        float s = 0.0f;
#pragma unroll
        for (int r = 0; r < 16; r++) s += red[r][tid];
        int j = j0 + tid;
        if (j < NH) g_pooled[b * NH + j] = s / (float)len;
    }
}

// ---------------- Kernel B: gate = sigmoid(pooled @ Wa + ba); out = gate * x ----
// grid = B/GB blocks, 320 threads; each block handles GB batches, thread j<300
// computes GB gate outputs, reusing each Wa element GB times.
constexpr int GB = 4;

__global__ __launch_bounds__(320)
void gate_kernel(const float* __restrict__ x,
                 const float* __restrict__ Wa,
                 const float* __restrict__ ba,
                 float*       __restrict__ out)
{
    __shared__ float ps[GB][NH];
    const int b0  = blockIdx.x * GB;
    const int tid = threadIdx.x;

    for (int i = tid; i < GB * NH; i += blockDim.x)
        ps[i / NH][i % NH] = g_pooled[(b0 + i / NH) * NH + i % NH];
    __syncthreads();

    const int j = tid;
    if (j < NC) {
        float acc[GB];
        float bav = ba[j];
#pragma unroll
        for (int g = 0; g < GB; g++) acc[g] = bav;

        for (int h = 0; h < NH; h++) {
            float w = Wa[(size_t)h * NC + j];
#pragma unroll
            for (int g = 0; g < GB; g++)
                acc[g] = fmaf(ps[g][h], w, acc[g]);
        }
#pragma unroll
        for (int g = 0; g < GB; g++) {
            float gate = 1.0f / (1.0f + expf(-acc[g]));
            out[(size_t)(b0 + g) * NC + j] = gate * x[(size_t)(b0 + g) * NC + j];
        }
    }
}

// ---------------- launch ----------------
// metadata order: x, context, lengths, W1, b1, Wa, ba
extern "C" void kernel_launch(void* const* d_in, const int* in_sizes, int n_in,
                              void* d_out, int out_size)
{
    const float* x       = (const float*)d_in[0];
    const float* context = (const float*)d_in[1];
    const int*   lengths = (const int*)  d_in[2];
    const float* W1      = (const float*)d_in[3];
    const float* b1      = (const float*)d_in[4];
    const float* Wa      = (const float*)d_in[5];
    const float* ba      = (const float*)d_in[6];
    float* out = (float*)d_out;

    dim3 gridA((NH + TN - 1) / TN, BB);
    pool_kernel<<<gridA, 128>>>(context, lengths, W1, b1);

    gate_kernel<<<BB / GB, 320>>>(x, Wa, ba, out);
}

// round 3
// speedup vs baseline: 3.3261x; 3.3261x over previous
#include <cuda_runtime.h>
#include <cuda_bf16.h>
#include <cstdint>

// ---------------- problem constants ----------------
#define BB     256
#define LMAXV  512
#define NC     300   // NCOND (K of GEMM1)
#define NH     600   // NHID  (N of GEMM1)
#define KPAD   320   // K padded to 10*32
#define NPAD   640   // N padded to 5*128

// ---------------- device scratch (no runtime allocs allowed) ----------------
__device__ float         g_pool[BB * NH];          // pooled SUMS (pre-division)
__device__ __nv_bfloat16 g_w1t_hi[NPAD * KPAD];    // W1^T split, [n][k]
__device__ __nv_bfloat16 g_w1t_lo[NPAD * KPAD];

// ---------------- helpers ----------------
__device__ __forceinline__ uint32_t s2u(const void* p) {
    uint32_t a;
    asm("{ .reg .u64 t; cvta.to.shared.u64 t, %1; cvt.u32.u64 %0, t; }" : "=r"(a) : "l"(p));
    return a;
}

__device__ __forceinline__ void ldm_x4(uint32_t* r, uint32_t addr) {
    asm volatile("ldmatrix.sync.aligned.m8n8.x4.shared.b16 {%0,%1,%2,%3}, [%4];"
                 : "=r"(r[0]), "=r"(r[1]), "=r"(r[2]), "=r"(r[3]) : "r"(addr));
}

__device__ __forceinline__ void mma_bf16(float* d, const uint32_t* a, const uint32_t* b) {
    asm volatile(
        "mma.sync.aligned.m16n8k16.row.col.f32.bf16.bf16.f32 "
        "{%0,%1,%2,%3}, {%4,%5,%6,%7}, {%8,%9}, {%0,%1,%2,%3};"
        : "+f"(d[0]), "+f"(d[1]), "+f"(d[2]), "+f"(d[3])
        : "r"(a[0]), "r"(a[1]), "r"(a[2]), "r"(a[3]), "r"(b[0]), "r"(b[1]));
}

// ---------------- prep: W1 -> W1^T hi/lo bf16, zero pooled sums ----------------
__global__ void prep_kernel(const float* __restrict__ W1) {
    int idx = blockIdx.x * blockDim.x + threadIdx.x;
    if (idx < NPAD * KPAD) {
        int n = idx / KPAD, k = idx % KPAD;
        float v = (n < NH && k < NC) ? W1[(size_t)k * NH + n] : 0.0f;
        __nv_bfloat16 hi = __float2bfloat16(v);
        g_w1t_hi[idx] = hi;
        g_w1t_lo[idx] = __float2bfloat16(v - __bfloat162float(hi));
    }
    if (idx < BB * NH) g_pool[idx] = 0.0f;
}

// ---------------- Kernel A: mma.sync fused GEMM1 + relu + masked pool ----------------
// grid = (nt=5, mt=4, b=256), 256 threads = 8 warps (4m x 2n), warp tile 32x64
__global__ __launch_bounds__(256, 2)
void mma_pool_kernel(const float* __restrict__ ctx,
                     const int*   __restrict__ lengths,
                     const float* __restrict__ b1)
{
    // SMEM tiles: 128 rows x 32 bf16 (64B) padded to 80B stride -> conflict-free ldmatrix
    __shared__ __align__(16) char sAhi[128 * 80];
    __shared__ __align__(16) char sAlo[128 * 80];
    __shared__ __align__(16) char sBhi[128 * 80];
    __shared__ __align__(16) char sBlo[128 * 80];
    __shared__ float sbias[128];
    __shared__ float sred[128];

    const int nt = blockIdx.x, mt = blockIdx.y, b = blockIdx.z;
    int len = lengths[b]; if (len < 1) len = 1;
    if (mt * 128 >= len) return;

    const int tid  = threadIdx.x;
    const int warp = tid >> 5, lane = tid & 31;
    const int warp_m = (warp & 3) * 32;   // 4 warps along M
    const int warp_n = (warp >> 2) * 64;  // 2 warps along N

    const int n0 = nt * 128;
    const size_t ctx_row0 = ((size_t)b * LMAXV + (size_t)mt * 128) * NC;

    // per-lane ldmatrix byte offsets (t = lane/8 selects the 8x8 tile)
    const int t = lane >> 3, r = lane & 7;
    const uint32_t aoff = (uint32_t)(((t & 1) * 8 + r) * 80 + (t >> 1) * 16);
    const uint32_t boff = (uint32_t)((((t >> 1) * 8) + r) * 80 + (t & 1) * 16);

    const uint32_t uAhi = s2u(sAhi), uAlo = s2u(sAlo);
    const uint32_t uBhi = s2u(sBhi), uBlo = s2u(sBlo);

    if (tid < 128) {
        int j = n0 + tid;
        sbias[tid] = (j < NH) ? b1[j] : 0.0f;
        sred[tid] = 0.0f;
    }

    float acc[2][8][4];
    #pragma unroll
    for (int i = 0; i < 2; i++)
        #pragma unroll
        for (int j = 0; j < 8; j++)
            #pragma unroll
            for (int q = 0; q < 4; q++) acc[i][j][q] = 0.0f;

    for (int c = 0; c < 10; c++) {
        __syncthreads();
        // ---- stage A: 128 tokens x 32 k, fp32 -> bf16 hi/lo split ----
        #pragma unroll
        for (int e = 0; e < 4; e++) {
            int idx = e * 256 + tid;            // 1024 float4 units
            int row = idx >> 3, f4 = idx & 7;
            int k = c * 32 + f4 * 4;
            float4 v = make_float4(0.f, 0.f, 0.f, 0.f);
            if (k < NC)
                v = *(const float4*)(ctx + ctx_row0 + (size_t)row * NC + k);
            __nv_bfloat162 h01 = __floats2bfloat162_rn(v.x, v.y);
            __nv_bfloat162 h23 = __floats2bfloat162_rn(v.z, v.w);
            float2 f01 = __bfloat1622float2(h01);
            float2 f23 = __bfloat1622float2(h23);
            __nv_bfloat162 l01 = __floats2bfloat162_rn(v.x - f01.x, v.y - f01.y);
            __nv_bfloat162 l23 = __floats2bfloat162_rn(v.z - f23.x, v.w - f23.y);
            *(uint2*)(sAhi + row * 80 + f4 * 8) =
                make_uint2(*(uint32_t*)&h01, *(uint32_t*)&h23);
            *(uint2*)(sAlo + row * 80 + f4 * 8) =
                make_uint2(*(uint32_t*)&l01, *(uint32_t*)&l23);
        }
        // ---- stage B: 128 n-rows x 32 k, pre-split bf16 ----
        #pragma unroll
        for (int e = 0; e < 2; e++) {
            int idx = e * 256 + tid;            // 512 uint4 units
            int row = idx >> 2, q = idx & 3;
            size_t src = (size_t)(n0 + row) * KPAD + c * 32 + q * 8;
            *(uint4*)(sBhi + row * 80 + q * 16) = *(const uint4*)(g_w1t_hi + src);
            *(uint4*)(sBlo + row * 80 + q * 16) = *(const uint4*)(g_w1t_lo + src);
        }
        __syncthreads();

        // ---- MMA: 2 k16 steps, 3-product split ----
        #pragma unroll
        for (int s = 0; s < 2; s++) {
            uint32_t ahi[2][4], alo[2][4];
            #pragma unroll
            for (int m2 = 0; m2 < 2; m2++) {
                uint32_t ab = (uint32_t)((warp_m + m2 * 16) * 80 + s * 32);
                ldm_x4(ahi[m2], uAhi + ab + aoff);
                ldm_x4(alo[m2], uAlo + ab + aoff);
            }
            #pragma unroll
            for (int np = 0; np < 4; np++) {
                uint32_t bh[4], bl[4];
                uint32_t bb = (uint32_t)((warp_n + np * 16) * 80 + s * 32);
                ldm_x4(bh, uBhi + bb + boff);
                ldm_x4(bl, uBlo + bb + boff);
                #pragma unroll
                for (int m2 = 0; m2 < 2; m2++) {
                    mma_bf16(acc[m2][2 * np],     ahi[m2], bh);
                    mma_bf16(acc[m2][2 * np + 1], ahi[m2], bh + 2);
                    mma_bf16(acc[m2][2 * np],     ahi[m2], bl);
                    mma_bf16(acc[m2][2 * np + 1], ahi[m2], bl + 2);
                    mma_bf16(acc[m2][2 * np],     alo[m2], bh);
                    mma_bf16(acc[m2][2 * np + 1], alo[m2], bh + 2);
                }
            }
        }
    }

    // ---- epilogue: bias + relu + row-mask + column sums ----
    __syncthreads();
    const int lrow = lane >> 2;           // 0..7
    const int lcol = (lane & 3) * 2;      // 0,2,4,6
    const int gm_base = mt * 128 + warp_m;

    #pragma unroll
    for (int n8 = 0; n8 < 8; n8++) {
        int nc = warp_n + n8 * 8 + lcol;
        float be = sbias[nc], bo = sbias[nc + 1];
        float se = 0.0f, so = 0.0f;
        #pragma unroll
        for (int m2 = 0; m2 < 2; m2++) {
            int row0 = gm_base + m2 * 16 + lrow;
            bool v0 = row0 < len;
            bool v1 = (row0 + 8) < len;
            const float* a = acc[m2][n8];
            if (v0) { se += fmaxf(a[0] + be, 0.0f); so += fmaxf(a[1] + bo, 0.0f); }
            if (v1) { se += fmaxf(a[2] + be, 0.0f); so += fmaxf(a[3] + bo, 0.0f); }
        }
        #pragma unroll
        for (int d = 4; d < 32; d <<= 1) {
            se += __shfl_xor_sync(0xffffffffu, se, d);
            so += __shfl_xor_sync(0xffffffffu, so, d);
        }
        if (lane < 4) {
            atomicAdd(&sred[nc], se);
            atomicAdd(&sred[nc + 1], so);
        }
    }
    __syncthreads();
    if (tid < 128) {
        int j = n0 + tid;
        if (j < NH) atomicAdd(&g_pool[(size_t)b * NH + j], sred[tid]);
    }
}

// ---------------- Kernel B: gate = sigmoid(pooled/len @ Wa + ba); out = gate * x ----
#define GB 2
__global__ __launch_bounds__(320)
void gate_kernel(const float* __restrict__ x,
                 const float* __restrict__ Wa,
                 const float* __restrict__ ba,
                 const int*   __restrict__ lengths,
                 float*       __restrict__ out)
{
    __shared__ float ps[GB][NH];
    const int b0 = blockIdx.x * GB, tid = threadIdx.x;

    float inv[GB];
    #pragma unroll
    for (int g = 0; g < GB; g++) {
        int len = lengths[b0 + g]; if (len < 1) len = 1;
        inv[g] = 1.0f / (float)len;
    }
    for (int i = tid; i < GB * NH; i += 320) {
        int g = i / NH, h = i % NH;
        ps[g][h] = g_pool[(size_t)(b0 + g) * NH + h] * inv[g];
    }
    __syncthreads();

    if (tid < NC) {
        float a0 = ba[tid], a1 = a0;
        #pragma unroll 8
        for (int h = 0; h < NH; h++) {
            float w = Wa[(size_t)h * NC + tid];
            a0 = fmaf(ps[0][h], w, a0);
            a1 = fmaf(ps[1][h], w, a1);
        }
        float g0 = 1.0f / (1.0f + expf(-a0));
        float g1 = 1.0f / (1.0f + expf(-a1));
        out[(size_t)b0 * NC + tid]       = g0 * x[(size_t)b0 * NC + tid];
        out[(size_t)(b0 + 1) * NC + tid] = g1 * x[(size_t)(b0 + 1) * NC + tid];
    }
}

// ---------------- launch ----------------
// metadata order: x, context, lengths, W1, b1, Wa, ba
extern "C" void kernel_launch(void* const* d_in, const int* in_sizes, int n_in,
                              void* d_out, int out_size)
{
    const float* x       = (const float*)d_in[0];
    const float* context = (const float*)d_in[1];
    const int*   lengths = (const int*)  d_in[2];
    const float* W1      = (const float*)d_in[3];
    const float* b1      = (const float*)d_in[4];
    const float* Wa      = (const float*)d_in[5];
    const float* ba      = (const float*)d_in[6];
    float* out = (float*)d_out;

    prep_kernel<<<(NPAD * KPAD + 255) / 256, 256>>>(W1);

    dim3 grid(5, 4, BB);
    mma_pool_kernel<<<grid, 256>>>(context, lengths, b1);

    gate_kernel<<<BB / GB, 320>>>(x, Wa, ba, lengths, out);
}